// round 13
// baseline (speedup 1.0000x reference)
#include <cuda_runtime.h>
#include <cuda_bf16.h>
#include <math.h>

#define BB 8
#define NN 2048
#define FIN 256
#define FO 64
#define ALPHA 0.2f

typedef unsigned long long u64;
typedef unsigned int u32;

// ---- HMMA m16n8k16 bf16 (base PTX, compiles for compute_103) ----
__device__ __forceinline__ void mma_bf16(float* c, const u32* a, u32 b0, u32 b1) {
    asm("mma.sync.aligned.m16n8k16.row.col.f32.bf16.bf16.f32 "
        "{%0,%1,%2,%3}, {%4,%5,%6,%7}, {%8,%9}, {%0,%1,%2,%3};"
        : "+f"(c[0]), "+f"(c[1]), "+f"(c[2]), "+f"(c[3])
        : "r"(a[0]), "r"(a[1]), "r"(a[2]), "r"(a[3]), "r"(b0), "r"(b1));
}

// split float pair -> bf16 hi / lo pairs
__device__ __forceinline__ void split2(float x, float y, u32& hi, u32& lo) {
    __nv_bfloat162 h2 = __float22bfloat162_rn(make_float2(x, y));
    float2 hf = __bfloat1622float2(h2);
    __nv_bfloat162 l2 = __float22bfloat162_rn(make_float2(x - hf.x, y - hf.y));
    hi = *(u32*)&h2;
    lo = *(u32*)&l2;
}

// ---- scratch ----
__device__ float g_Wh[BB * NN * FO];
__device__ float g_s1[BB * NN];
__device__ float g_s2[BB * NN];
__device__ float g_s2max[BB];
__device__ __nv_bfloat16 g_WhT_hi[BB * FO * NN];   // [b][o][j]
__device__ __nv_bfloat16 g_WhT_lo[BB * FO * NN];
__device__ float g_pacc[2 * BB * NN * FO];          // j-half partials
__device__ float g_pl[2 * BB * NN];

#define SP 72   // smem tile stride (bf16): frag LDS bank = 4g+t, conflict-free

// ============================================================
// Kernel A: Wh = h @ W^T via HMMA bf16 3-term split.
// 512 blocks x 32 rows, 128 thr (4 warps = 2 rowgrp x 2 nhalf),
// K = 256 in 4 chunks of 64. h/W split to bf16 hi+lo in staging.
// ============================================================
__global__ __launch_bounds__(128) void kernelA(const float* __restrict__ h,
                                               const float* __restrict__ Wm) {
    __shared__ __align__(16) __nv_bfloat16 Ahi[32 * SP], Alo[32 * SP];
    __shared__ __align__(16) __nv_bfloat16 Bhi[64 * SP], Blo[64 * SP];

    const int tid  = threadIdx.x;
    const int wid  = tid >> 5, lane = tid & 31;
    const int g    = lane >> 2, t = lane & 3;
    const int r0   = blockIdx.x * 32;
    const int rg   = wid & 1;        // row group: rows rg*16..+15
    const int nh   = wid >> 1;       // n half:  nf = nh*4..+3

    float acc[4][4];
#pragma unroll
    for (int f = 0; f < 4; f++)
#pragma unroll
        for (int c = 0; c < 4; c++) acc[f][c] = 0.0f;

    const int arow = tid >> 2, afq = tid & 3;     // A staging: 32 rows x 4 f-quarters
    const int wo   = tid >> 1, wfh = tid & 1;     // W staging: 64 o x 2 f-halves

    for (int fc = 0; fc < FIN; fc += 64) {
        __syncthreads();
        // stage A (h rows, hi/lo split)
        {
            const float* hp = h + (size_t)(r0 + arow) * FIN + fc + afq * 16;
            __nv_bfloat16* dh = Ahi + arow * SP + afq * 16;
            __nv_bfloat16* dl = Alo + arow * SP + afq * 16;
#pragma unroll
            for (int q = 0; q < 4; q++) {
                float4 v = *(const float4*)(hp + q * 4);
                u32 h0, l0, h1, l1;
                split2(v.x, v.y, h0, l0);
                split2(v.z, v.w, h1, l1);
                *(u32*)(dh + q * 4)     = h0;
                *(u32*)(dh + q * 4 + 2) = h1;
                *(u32*)(dl + q * 4)     = l0;
                *(u32*)(dl + q * 4 + 2) = l1;
            }
        }
        // stage W (B: [n=o][k=f], hi/lo split)
        {
            const float* wp = Wm + (size_t)wo * FIN + fc + wfh * 32;
            __nv_bfloat16* dh = Bhi + wo * SP + wfh * 32;
            __nv_bfloat16* dl = Blo + wo * SP + wfh * 32;
#pragma unroll
            for (int q = 0; q < 8; q++) {
                float4 v = *(const float4*)(wp + q * 4);
                u32 h0, l0, h1, l1;
                split2(v.x, v.y, h0, l0);
                split2(v.z, v.w, h1, l1);
                *(u32*)(dh + q * 4)     = h0;
                *(u32*)(dh + q * 4 + 2) = h1;
                *(u32*)(dl + q * 4)     = l0;
                *(u32*)(dl + q * 4 + 2) = l1;
            }
        }
        __syncthreads();

        // mma: 4 k-frags x 4 n-frags x 3 terms
#pragma unroll
        for (int kf = 0; kf < 4; kf++) {
            int k0 = kf * 16;
            int ra = (rg * 16 + g) * SP + k0 + 2 * t;
            int rb = ra + 8 * SP;
            u32 ah[4], al[4];
            ah[0] = *(const u32*)&Ahi[ra];      ah[1] = *(const u32*)&Ahi[rb];
            ah[2] = *(const u32*)&Ahi[ra + 8];  ah[3] = *(const u32*)&Ahi[rb + 8];
            al[0] = *(const u32*)&Alo[ra];      al[1] = *(const u32*)&Alo[rb];
            al[2] = *(const u32*)&Alo[ra + 8];  al[3] = *(const u32*)&Alo[rb + 8];
#pragma unroll
            for (int f = 0; f < 4; f++) {
                int nf = nh * 4 + f;
                int bo = (nf * 8 + g) * SP + k0 + 2 * t;
                u32 bh0 = *(const u32*)&Bhi[bo], bh1 = *(const u32*)&Bhi[bo + 8];
                u32 bl0 = *(const u32*)&Blo[bo], bl1 = *(const u32*)&Blo[bo + 8];
                mma_bf16(acc[f], ah, bh0, bh1);
                mma_bf16(acc[f], al, bh0, bh1);
                mma_bf16(acc[f], ah, bl0, bl1);
            }
        }
    }

    // store Wh fp32 (D frag map: c0=(g,2t) c1=(g,2t+1) c2/c3 row g+8)
    float* whp = g_Wh + (size_t)(r0 + rg * 16) * FO;
#pragma unroll
    for (int f = 0; f < 4; f++) {
        int col = (nh * 4 + f) * 8 + 2 * t;
        *(float2*)&whp[(size_t)g * FO + col]       = make_float2(acc[f][0], acc[f][1]);
        *(float2*)&whp[(size_t)(g + 8) * FO + col] = make_float2(acc[f][2], acc[f][3]);
    }
}

// ============================================================
// Kernel A2: Wh -> WhT[b][o][j] bf16 hi+lo, FUSED s1/s2.
// grid (32 j-tiles, 8 b), 256 thr.
// ============================================================
__global__ __launch_bounds__(256) void kernelA2(const float* __restrict__ av) {
    __shared__ float sm[64 * 65];
    const int tid = threadIdx.x;
    const int j0  = blockIdx.x * 64;
    const int b   = blockIdx.y;

    {
        int j = tid >> 2, u = tid & 3;
        const float* src = g_Wh + ((size_t)b * NN + j0 + j) * FO + u * 16;
        float* dst = sm + j * 65 + u * 16;
        float s1p = 0.0f, s2p = 0.0f;
#pragma unroll
        for (int q = 0; q < 4; q++) {
            float4 v = *(const float4*)(src + q * 4);
            dst[q * 4 + 0] = v.x;   // scalar STS (260B pitch not 16B-aligned)
            dst[q * 4 + 1] = v.y;
            dst[q * 4 + 2] = v.z;
            dst[q * 4 + 3] = v.w;
            int o = u * 16 + q * 4;
            s1p += v.x * __ldg(av + o)     + v.y * __ldg(av + o + 1)
                 + v.z * __ldg(av + o + 2) + v.w * __ldg(av + o + 3);
            s2p += v.x * __ldg(av + FO + o)     + v.y * __ldg(av + FO + o + 1)
                 + v.z * __ldg(av + FO + o + 2) + v.w * __ldg(av + FO + o + 3);
        }
        s1p += __shfl_down_sync(0xffffffffu, s1p, 2, 4);
        s1p += __shfl_down_sync(0xffffffffu, s1p, 1, 4);
        s2p += __shfl_down_sync(0xffffffffu, s2p, 2, 4);
        s2p += __shfl_down_sync(0xffffffffu, s2p, 1, 4);
        if (u == 0) { g_s1[b * NN + j0 + j] = s1p; g_s2[b * NN + j0 + j] = s2p; }
    }
    __syncthreads();
    {
        int o = tid >> 2, q = tid & 3;
        u32 hiw[8], low[8];
#pragma unroll
        for (int p = 0; p < 8; p++) {
            float f0 = sm[(q * 16 + 2 * p)     * 65 + o];
            float f1 = sm[(q * 16 + 2 * p + 1) * 65 + o];
            split2(f0, f1, hiw[p], low[p]);
        }
        size_t idx = ((size_t)b * FO + o) * NN + j0 + q * 16;
        *(uint4*)(g_WhT_hi + idx)     = make_uint4(hiw[0], hiw[1], hiw[2], hiw[3]);
        *(uint4*)(g_WhT_hi + idx + 8) = make_uint4(hiw[4], hiw[5], hiw[6], hiw[7]);
        *(uint4*)(g_WhT_lo + idx)     = make_uint4(low[0], low[1], low[2], low[3]);
        *(uint4*)(g_WhT_lo + idx + 8) = make_uint4(low[4], low[5], low[6], low[7]);
    }
}

// ============================================================
// Kernel B: per-batch max of s2
// ============================================================
__global__ void kernelB() {
    __shared__ float red[256];
    int b = blockIdx.x, tid = threadIdx.x;
    float m = -1e30f;
    for (int j = tid; j < NN; j += 256) m = fmaxf(m, g_s2[b * NN + j]);
    red[tid] = m;
    __syncthreads();
    for (int s = 128; s > 0; s >>= 1) {
        if (tid < s) red[tid] = fmaxf(red[tid], red[tid + s]);
        __syncthreads();
    }
    if (tid == 0) g_s2max[b] = red[0];
}

// ============================================================
// Kernel C: masked softmax + P@Wh via HMMA, double-buffered,
// ONE sync per chunk. grid (jh=2, 32 i-tiles, 8 b) = 512 blocks,
// 256 thr = 8 warps: 4 rowgroups x 2 n-halves (i-tile 64).
// Buffer = Phi,Plo (64xSP) + Whi,Wlo (64xSP) = 36 KB; x2 = 72 KB
// -> 3 blocks/SM. Safety: stage(c+2) is after sync(c+1) which is
// after all warps' mma(c) -> no WAR hazard on buffers.
// ============================================================
#define CBUF (4 * 64 * SP)         // bf16 elems per buffer (18432)
#define DSMEM_BYTES (2 * CBUF * 2) // 73728 B

__global__ __launch_bounds__(256) void kernelC(const int* __restrict__ adj) {
    extern __shared__ __align__(16) __nv_bfloat16 dsm[];
    __shared__ float ls[64];

    const int tid  = threadIdx.x;
    const int wid  = tid >> 5, lane = tid & 31;
    const int g    = lane >> 2, t = lane & 3;
    const int jh   = blockIdx.x;
    const int i0   = blockIdx.y * 64;
    const int b    = blockIdx.z;
    const int j0   = jh * (NN / 2);
    const int rg   = wid & 3;        // mma rows rg*16..+15
    const int nh   = wid >> 2;       // nf = nh*4..+3

    const float M = g_s2max[b];
    float s1v[8], lsum[8];
#pragma unroll
    for (int ii = 0; ii < 8; ii++) {
        s1v[ii]  = __ldg(&g_s1[b * NN + i0 + wid * 8 + ii]);
        lsum[ii] = 0.0f;
    }

    const int*   adjb = adj + ((size_t)b * NN + i0) * NN;
    const float* s2b  = g_s2 + b * NN;
    const __nv_bfloat16* bhiB = g_WhT_hi + (size_t)b * FO * NN;
    const __nv_bfloat16* bloB = g_WhT_lo + (size_t)b * FO * NN;

    float acc[4][4];
#pragma unroll
    for (int f = 0; f < 4; f++)
#pragma unroll
        for (int c = 0; c < 4; c++) acc[f][c] = 0.0f;

    const int so = tid >> 2, sq = tid & 3;   // W staging map

    for (int tch = 0; tch < NN / 2 / 64; tch++) {
        const int jt = j0 + tch * 64;
        __nv_bfloat16* base = dsm + (tch & 1) * CBUF;
        __nv_bfloat16* Phi = base;
        __nv_bfloat16* Plo = base + 64 * SP;
        __nv_bfloat16* Whi = base + 2 * 64 * SP;
        __nv_bfloat16* Wlo = base + 3 * 64 * SP;

        // ---- stage W tiles ----
        {
            const __nv_bfloat16* sh = bhiB + (size_t)so * NN + jt + sq * 16;
            const __nv_bfloat16* sl = bloB + (size_t)so * NN + jt + sq * 16;
            *(uint4*)&Whi[so * SP + sq * 16]     = *(const uint4*)(sh);
            *(uint4*)&Whi[so * SP + sq * 16 + 8] = *(const uint4*)(sh + 8);
            *(uint4*)&Wlo[so * SP + sq * 16]     = *(const uint4*)(sl);
            *(uint4*)&Wlo[so * SP + sq * 16 + 8] = *(const uint4*)(sl + 8);
        }
        // ---- phase 1: p = exp(LR(s1+s2)-m) masked, hi/lo split ----
        {
            float2 s2j = *(const float2*)(s2b + jt + 2 * lane);
#pragma unroll
            for (int ii = 0; ii < 8; ii++) {
                int i = wid * 8 + ii;
                int2 a = *(const int2*)(adjb + (size_t)i * NN + jt + 2 * lane);
                float tt = s1v[ii] + M;
                float mi = fmaxf(tt, ALPHA * tt);
                float e0 = s1v[ii] + s2j.x;
                float e1 = s1v[ii] + s2j.y;
                e0 = fmaxf(e0, ALPHA * e0);
                e1 = fmaxf(e1, ALPHA * e1);
                float p0 = (a.x > 0) ? __expf(e0 - mi) : 0.0f;
                float p1 = (a.y > 0) ? __expf(e1 - mi) : 0.0f;
                lsum[ii] += p0 + p1;
                u32 hi2, lo2;
                split2(p0, p1, hi2, lo2);
                *(u32*)&Phi[i * SP + 2 * lane] = hi2;
                *(u32*)&Plo[i * SP + 2 * lane] = lo2;
            }
        }
        __syncthreads();

        // ---- phase 2: HMMA 3-term ----
#pragma unroll
        for (int kf = 0; kf < 4; kf++) {
            int k0 = kf * 16;
            int ra = (rg * 16 + g) * SP + k0 + 2 * t;
            int rb = ra + 8 * SP;
            u32 ah[4], al[4];
            ah[0] = *(const u32*)&Phi[ra];      ah[1] = *(const u32*)&Phi[rb];
            ah[2] = *(const u32*)&Phi[ra + 8];  ah[3] = *(const u32*)&Phi[rb + 8];
            al[0] = *(const u32*)&Plo[ra];      al[1] = *(const u32*)&Plo[rb];
            al[2] = *(const u32*)&Plo[ra + 8];  al[3] = *(const u32*)&Plo[rb + 8];
#pragma unroll
            for (int f = 0; f < 4; f++) {
                int nf = nh * 4 + f;
                int bo = (nf * 8 + g) * SP + k0 + 2 * t;
                u32 bh0 = *(const u32*)&Whi[bo], bh1 = *(const u32*)&Whi[bo + 8];
                u32 bl0 = *(const u32*)&Wlo[bo], bl1 = *(const u32*)&Wlo[bo + 8];
                mma_bf16(acc[f], ah, bh0, bh1);
                mma_bf16(acc[f], al, bh0, bh1);
                mma_bf16(acc[f], ah, bl0, bl1);
            }
        }
    }

    // ---- row sums ----
#pragma unroll
    for (int ii = 0; ii < 8; ii++) {
        float v = lsum[ii];
#pragma unroll
        for (int off = 16; off >= 1; off >>= 1)
            v += __shfl_xor_sync(0xffffffffu, v, off);
        if (lane == 0) ls[wid * 8 + ii] = v;
    }
    __syncthreads();
    if (tid < 64)
        g_pl[jh * BB * NN + b * NN + i0 + tid] = ls[tid];

    // ---- store partials ----
    float* pacc = g_pacc + (size_t)jh * BB * NN * FO
                + ((size_t)b * NN + i0 + rg * 16) * FO;
#pragma unroll
    for (int f = 0; f < 4; f++) {
        int col = (nh * 4 + f) * 8 + 2 * t;
        *(float2*)&pacc[(size_t)g * FO + col]       = make_float2(acc[f][0], acc[f][1]);
        *(float2*)&pacc[(size_t)(g + 8) * FO + col] = make_float2(acc[f][2], acc[f][3]);
    }
}

// ============================================================
// Kernel D: combine halves, normalize, ELU, store
// ============================================================
__global__ __launch_bounds__(256) void kernelD(float* __restrict__ out) {
    int idx = blockIdx.x * 256 + threadIdx.x;   // float4 index
    int row = idx >> 4;
    float l  = g_pl[row] + g_pl[BB * NN + row];
    float rl = 1.0f / l;
    float4 a0 = *(const float4*)(g_pacc + (size_t)idx * 4);
    float4 a1 = *(const float4*)(g_pacc + (size_t)BB * NN * FO + (size_t)idx * 4);
    float4 r;
    r.x = (a0.x + a1.x) * rl; r.x = (r.x > 0.0f) ? r.x : expm1f(r.x);
    r.y = (a0.y + a1.y) * rl; r.y = (r.y > 0.0f) ? r.y : expm1f(r.y);
    r.z = (a0.z + a1.z) * rl; r.z = (r.z > 0.0f) ? r.z : expm1f(r.z);
    r.w = (a0.w + a1.w) * rl; r.w = (r.w > 0.0f) ? r.w : expm1f(r.w);
    *(float4*)(out + (size_t)idx * 4) = r;
}

// ============================================================
extern "C" void kernel_launch(void* const* d_in, const int* in_sizes, int n_in,
                              void* d_out, int out_size) {
    const float* h   = nullptr;
    const float* Wm  = nullptr;
    const float* av  = nullptr;
    const int*   adj = nullptr;
    for (int i = 0; i < n_in; i++) {
        switch (in_sizes[i]) {
            case BB * NN * FIN: h  = (const float*)d_in[i]; break;
            case FO * FIN:      Wm = (const float*)d_in[i]; break;
            case 2 * FO:        av = (const float*)d_in[i]; break;
            default:
                if (in_sizes[i] == (int)((size_t)BB * NN * NN))
                    adj = (const int*)d_in[i];
                break;
        }
    }
    float* out = (float*)d_out;

    cudaFuncSetAttribute(kernelC, cudaFuncAttributeMaxDynamicSharedMemorySize,
                         DSMEM_BYTES);

    kernelA<<<BB * NN / 32, 128>>>(h, Wm);
    kernelA2<<<dim3(NN / 64, BB), 256>>>(av);
    kernelB<<<BB, 256>>>();
    kernelC<<<dim3(2, NN / 64, BB), 256, DSMEM_BYTES>>>(adj);
    kernelD<<<BB * NN * FO / 4 / 256, 256>>>(out);
}

// round 15
// speedup vs baseline: 1.6429x; 1.6429x over previous
#include <cuda_runtime.h>
#include <cuda_bf16.h>
#include <math.h>

#define BB 8
#define NN 2048
#define FIN 256
#define FO 64
#define ALPHA 0.2f

typedef unsigned long long u64;
typedef unsigned int u32;

// ---- HMMA m16n8k16 bf16 (base PTX, compiles for compute_103) ----
__device__ __forceinline__ void mma_bf16(float* c, const u32* a, u32 b0, u32 b1) {
    asm("mma.sync.aligned.m16n8k16.row.col.f32.bf16.bf16.f32 "
        "{%0,%1,%2,%3}, {%4,%5,%6,%7}, {%8,%9}, {%0,%1,%2,%3};"
        : "+f"(c[0]), "+f"(c[1]), "+f"(c[2]), "+f"(c[3])
        : "r"(a[0]), "r"(a[1]), "r"(a[2]), "r"(a[3]), "r"(b0), "r"(b1));
}

// split float pair -> bf16 hi / lo pairs
__device__ __forceinline__ void split2(float x, float y, u32& hi, u32& lo) {
    __nv_bfloat162 h2 = __float22bfloat162_rn(make_float2(x, y));
    float2 hf = __bfloat1622float2(h2);
    __nv_bfloat162 l2 = __float22bfloat162_rn(make_float2(x - hf.x, y - hf.y));
    hi = *(u32*)&h2;
    lo = *(u32*)&l2;
}

// ---- scratch ----
__device__ float g_Wh[BB * NN * FO];
__device__ float g_s1[BB * NN];
__device__ float g_s2[BB * NN];
__device__ float g_s2max[BB];
__device__ __nv_bfloat16 g_WhT_hi[BB * FO * NN];   // [b][o][j]
__device__ __nv_bfloat16 g_WhT_lo[BB * FO * NN];
__device__ float g_pacc[2 * BB * NN * FO];          // j-half partials
__device__ float g_pl[2 * BB * NN];

#define SP 72   // smem tile stride (bf16): frag LDS bank = 4g+t, conflict-free

// ============================================================
// Kernel A: Wh = h @ W^T via HMMA bf16 3-term split (proven)
// ============================================================
__global__ __launch_bounds__(128) void kernelA(const float* __restrict__ h,
                                               const float* __restrict__ Wm) {
    __shared__ __align__(16) __nv_bfloat16 Ahi[32 * SP], Alo[32 * SP];
    __shared__ __align__(16) __nv_bfloat16 Bhi[64 * SP], Blo[64 * SP];

    const int tid  = threadIdx.x;
    const int wid  = tid >> 5, lane = tid & 31;
    const int g    = lane >> 2, t = lane & 3;
    const int r0   = blockIdx.x * 32;
    const int rg   = wid & 1;
    const int nh   = wid >> 1;

    float acc[4][4];
#pragma unroll
    for (int f = 0; f < 4; f++)
#pragma unroll
        for (int c = 0; c < 4; c++) acc[f][c] = 0.0f;

    const int arow = tid >> 2, afq = tid & 3;
    const int wo   = tid >> 1, wfh = tid & 1;

    for (int fc = 0; fc < FIN; fc += 64) {
        __syncthreads();
        {
            const float* hp = h + (size_t)(r0 + arow) * FIN + fc + afq * 16;
            __nv_bfloat16* dh = Ahi + arow * SP + afq * 16;
            __nv_bfloat16* dl = Alo + arow * SP + afq * 16;
#pragma unroll
            for (int q = 0; q < 4; q++) {
                float4 v = *(const float4*)(hp + q * 4);
                u32 h0, l0, h1, l1;
                split2(v.x, v.y, h0, l0);
                split2(v.z, v.w, h1, l1);
                *(u32*)(dh + q * 4)     = h0;
                *(u32*)(dh + q * 4 + 2) = h1;
                *(u32*)(dl + q * 4)     = l0;
                *(u32*)(dl + q * 4 + 2) = l1;
            }
        }
        {
            const float* wp = Wm + (size_t)wo * FIN + fc + wfh * 32;
            __nv_bfloat16* dh = Bhi + wo * SP + wfh * 32;
            __nv_bfloat16* dl = Blo + wo * SP + wfh * 32;
#pragma unroll
            for (int q = 0; q < 8; q++) {
                float4 v = *(const float4*)(wp + q * 4);
                u32 h0, l0, h1, l1;
                split2(v.x, v.y, h0, l0);
                split2(v.z, v.w, h1, l1);
                *(u32*)(dh + q * 4)     = h0;
                *(u32*)(dh + q * 4 + 2) = h1;
                *(u32*)(dl + q * 4)     = l0;
                *(u32*)(dl + q * 4 + 2) = l1;
            }
        }
        __syncthreads();

#pragma unroll
        for (int kf = 0; kf < 4; kf++) {
            int k0 = kf * 16;
            int ra = (rg * 16 + g) * SP + k0 + 2 * t;
            int rb = ra + 8 * SP;
            u32 ah[4], al[4];
            ah[0] = *(const u32*)&Ahi[ra];      ah[1] = *(const u32*)&Ahi[rb];
            ah[2] = *(const u32*)&Ahi[ra + 8];  ah[3] = *(const u32*)&Ahi[rb + 8];
            al[0] = *(const u32*)&Alo[ra];      al[1] = *(const u32*)&Alo[rb];
            al[2] = *(const u32*)&Alo[ra + 8];  al[3] = *(const u32*)&Alo[rb + 8];
#pragma unroll
            for (int f = 0; f < 4; f++) {
                int nf = nh * 4 + f;
                int bo = (nf * 8 + g) * SP + k0 + 2 * t;
                u32 bh0 = *(const u32*)&Bhi[bo], bh1 = *(const u32*)&Bhi[bo + 8];
                u32 bl0 = *(const u32*)&Blo[bo], bl1 = *(const u32*)&Blo[bo + 8];
                mma_bf16(acc[f], ah, bh0, bh1);
                mma_bf16(acc[f], al, bh0, bh1);
                mma_bf16(acc[f], ah, bl0, bl1);
            }
        }
    }

    float* whp = g_Wh + (size_t)(r0 + rg * 16) * FO;
#pragma unroll
    for (int f = 0; f < 4; f++) {
        int col = (nh * 4 + f) * 8 + 2 * t;
        *(float2*)&whp[(size_t)g * FO + col]       = make_float2(acc[f][0], acc[f][1]);
        *(float2*)&whp[(size_t)(g + 8) * FO + col] = make_float2(acc[f][2], acc[f][3]);
    }
}

// ============================================================
// Kernel A2: Wh -> WhT[b][o][j] bf16 hi+lo, FUSED s1/s2 (proven)
// ============================================================
__global__ __launch_bounds__(256) void kernelA2(const float* __restrict__ av) {
    __shared__ float sm[64 * 65];
    const int tid = threadIdx.x;
    const int j0  = blockIdx.x * 64;
    const int b   = blockIdx.y;

    {
        int j = tid >> 2, u = tid & 3;
        const float* src = g_Wh + ((size_t)b * NN + j0 + j) * FO + u * 16;
        float* dst = sm + j * 65 + u * 16;
        float s1p = 0.0f, s2p = 0.0f;
#pragma unroll
        for (int q = 0; q < 4; q++) {
            float4 v = *(const float4*)(src + q * 4);
            dst[q * 4 + 0] = v.x;
            dst[q * 4 + 1] = v.y;
            dst[q * 4 + 2] = v.z;
            dst[q * 4 + 3] = v.w;
            int o = u * 16 + q * 4;
            s1p += v.x * __ldg(av + o)     + v.y * __ldg(av + o + 1)
                 + v.z * __ldg(av + o + 2) + v.w * __ldg(av + o + 3);
            s2p += v.x * __ldg(av + FO + o)     + v.y * __ldg(av + FO + o + 1)
                 + v.z * __ldg(av + FO + o + 2) + v.w * __ldg(av + FO + o + 3);
        }
        s1p += __shfl_down_sync(0xffffffffu, s1p, 2, 4);
        s1p += __shfl_down_sync(0xffffffffu, s1p, 1, 4);
        s2p += __shfl_down_sync(0xffffffffu, s2p, 2, 4);
        s2p += __shfl_down_sync(0xffffffffu, s2p, 1, 4);
        if (u == 0) { g_s1[b * NN + j0 + j] = s1p; g_s2[b * NN + j0 + j] = s2p; }
    }
    __syncthreads();
    {
        int o = tid >> 2, q = tid & 3;
        u32 hiw[8], low[8];
#pragma unroll
        for (int p = 0; p < 8; p++) {
            float f0 = sm[(q * 16 + 2 * p)     * 65 + o];
            float f1 = sm[(q * 16 + 2 * p + 1) * 65 + o];
            split2(f0, f1, hiw[p], low[p]);
        }
        size_t idx = ((size_t)b * FO + o) * NN + j0 + q * 16;
        *(uint4*)(g_WhT_hi + idx)     = make_uint4(hiw[0], hiw[1], hiw[2], hiw[3]);
        *(uint4*)(g_WhT_hi + idx + 8) = make_uint4(hiw[4], hiw[5], hiw[6], hiw[7]);
        *(uint4*)(g_WhT_lo + idx)     = make_uint4(low[0], low[1], low[2], low[3]);
        *(uint4*)(g_WhT_lo + idx + 8) = make_uint4(low[4], low[5], low[6], low[7]);
    }
}

// ============================================================
// Kernel B: per-batch max of s2
// ============================================================
__global__ void kernelB() {
    __shared__ float red[256];
    int b = blockIdx.x, tid = threadIdx.x;
    float m = -1e30f;
    for (int j = tid; j < NN; j += 256) m = fmaxf(m, g_s2[b * NN + j]);
    red[tid] = m;
    __syncthreads();
    for (int s = 128; s > 0; s >>= 1) {
        if (tid < s) red[tid] = fmaxf(red[tid], red[tid + s]);
        __syncthreads();
    }
    if (tid == 0) g_s2max[b] = red[0];
}

// ============================================================
// Kernel C: masked softmax + P@Wh via HMMA. i-tile 128, single
// buffer, 512 thr, launch_bounds(512,2) -> regs<=64, 55KB smem
// -> 2 blocks/SM = 32 warps (50% occ). 16 warps = 8 rowgroups
// x 2 n-halves. Phase1: thread = 4 rows x 4 j (int4 adj).
// W staging: uint4 = 8 bf16 per thread (R14 bug: uint2 left
// half the tile unwritten). m_i = LR(s1_i+max s2) bound ->
// single pass; halves additive; kernelD combines.
// ============================================================
#define CELEMS (384 * SP)            // bf16 elems (Phi,Plo:128*SP; Whi,Wlo:64*SP)
#define DSMEM_BYTES (CELEMS * 2)     // 55296 B

__global__ __launch_bounds__(512, 2) void kernelC(const int* __restrict__ adj) {
    extern __shared__ __align__(16) __nv_bfloat16 dsm[];
    __nv_bfloat16* Phi = dsm;
    __nv_bfloat16* Plo = dsm + 128 * SP;
    __nv_bfloat16* Whi = dsm + 256 * SP;
    __nv_bfloat16* Wlo = dsm + 320 * SP;
    __shared__ float ls[128];

    const int tid  = threadIdx.x;
    const int wid  = tid >> 5, lane = tid & 31;
    const int g    = lane >> 2, t = lane & 3;
    const int jh   = blockIdx.x;
    const int i0   = blockIdx.y * 128;
    const int b    = blockIdx.z;
    const int j0   = jh * (NN / 2);

    // phase-1 mapping: 4 rows x 4 j per thread
    const int rq = tid >> 4;        // 0..31 -> rows rq*4..+3
    const int jq = tid & 15;        // j = jq*4..+3
    // mma mapping: 16 warps = 8 rowgroups x 2 n-halves
    const int rg = wid & 7, nh = wid >> 3;
    // W staging: uint4 = 8 bf16 per thread (64 rows x 8 chunks)
    const int so = tid >> 3, sq = tid & 7;

    const float M = g_s2max[b];
    float s1r[4], lsum[4];
#pragma unroll
    for (int k = 0; k < 4; k++) {
        s1r[k]  = __ldg(&g_s1[b * NN + i0 + rq * 4 + k]);
        lsum[k] = 0.0f;
    }

    const int*   adjb = adj + ((size_t)b * NN + i0) * NN;
    const float* s2b  = g_s2 + b * NN;
    const __nv_bfloat16* bhiB = g_WhT_hi + (size_t)b * FO * NN;
    const __nv_bfloat16* bloB = g_WhT_lo + (size_t)b * FO * NN;

    float acc[4][4];
#pragma unroll
    for (int f = 0; f < 4; f++)
#pragma unroll
        for (int c = 0; c < 4; c++) acc[f][c] = 0.0f;

    for (int tch = 0; tch < NN / 2 / 64; tch++) {
        const int jt = j0 + tch * 64;

        // ---- stage W tiles: one uint4 (8 bf16) per thread ----
        *(uint4*)&Whi[so * SP + sq * 8] =
            *(const uint4*)(bhiB + (size_t)so * NN + jt + sq * 8);
        *(uint4*)&Wlo[so * SP + sq * 8] =
            *(const uint4*)(bloB + (size_t)so * NN + jt + sq * 8);

        // ---- phase 1: p = exp(LR(s1+s2)-m) masked, hi/lo split ----
        {
            float4 s2j = *(const float4*)(s2b + jt + jq * 4);
#pragma unroll
            for (int k = 0; k < 4; k++) {
                int i = rq * 4 + k;
                int4 a = *(const int4*)(adjb + (size_t)i * NN + jt + jq * 4);
                float s1 = s1r[k];
                float tt = s1 + M;
                float mi = fmaxf(tt, ALPHA * tt);
                float e0 = s1 + s2j.x, e1 = s1 + s2j.y;
                float e2 = s1 + s2j.z, e3 = s1 + s2j.w;
                e0 = fmaxf(e0, ALPHA * e0);
                e1 = fmaxf(e1, ALPHA * e1);
                e2 = fmaxf(e2, ALPHA * e2);
                e3 = fmaxf(e3, ALPHA * e3);
                float p0 = (a.x > 0) ? __expf(e0 - mi) : 0.0f;
                float p1 = (a.y > 0) ? __expf(e1 - mi) : 0.0f;
                float p2 = (a.z > 0) ? __expf(e2 - mi) : 0.0f;
                float p3 = (a.w > 0) ? __expf(e3 - mi) : 0.0f;
                lsum[k] += (p0 + p1) + (p2 + p3);
                u32 h0, l0, h1, l1;
                split2(p0, p1, h0, l0);
                split2(p2, p3, h1, l1);
                *(u32*)&Phi[i * SP + jq * 4]     = h0;
                *(u32*)&Phi[i * SP + jq * 4 + 2] = h1;
                *(u32*)&Plo[i * SP + jq * 4]     = l0;
                *(u32*)&Plo[i * SP + jq * 4 + 2] = l1;
            }
        }
        __syncthreads();

        // ---- phase 2: HMMA 3-term, 16 warps ----
#pragma unroll
        for (int kf = 0; kf < 4; kf++) {
            int k0 = kf * 16;
            int ra = (rg * 16 + g) * SP + k0 + 2 * t;
            int rb = ra + 8 * SP;
            u32 ah[4], al[4];
            ah[0] = *(const u32*)&Phi[ra];      ah[1] = *(const u32*)&Phi[rb];
            ah[2] = *(const u32*)&Phi[ra + 8];  ah[3] = *(const u32*)&Phi[rb + 8];
            al[0] = *(const u32*)&Plo[ra];      al[1] = *(const u32*)&Plo[rb];
            al[2] = *(const u32*)&Plo[ra + 8];  al[3] = *(const u32*)&Plo[rb + 8];
#pragma unroll
            for (int f = 0; f < 4; f++) {
                int nf = nh * 4 + f;
                int bo = (nf * 8 + g) * SP + k0 + 2 * t;
                u32 bh0 = *(const u32*)&Whi[bo], bh1 = *(const u32*)&Whi[bo + 8];
                u32 bl0 = *(const u32*)&Wlo[bo], bl1 = *(const u32*)&Wlo[bo + 8];
                mma_bf16(acc[f], ah, bh0, bh1);
                mma_bf16(acc[f], al, bh0, bh1);
                mma_bf16(acc[f], ah, bl0, bl1);
            }
        }
        __syncthreads();
    }

    // ---- row sums: reduce over 16 j-lanes ----
#pragma unroll
    for (int k = 0; k < 4; k++) {
        float v = lsum[k];
#pragma unroll
        for (int off = 8; off >= 1; off >>= 1)
            v += __shfl_down_sync(0xffffffffu, v, off, 16);
        if (jq == 0) ls[rq * 4 + k] = v;
    }
    __syncthreads();
    if (tid < 128)
        g_pl[jh * BB * NN + b * NN + i0 + tid] = ls[tid];

    // ---- store partials ----
    float* pacc = g_pacc + (size_t)jh * BB * NN * FO
                + ((size_t)b * NN + i0 + rg * 16) * FO;
#pragma unroll
    for (int f = 0; f < 4; f++) {
        int col = (nh * 4 + f) * 8 + 2 * t;
        *(float2*)&pacc[(size_t)g * FO + col]       = make_float2(acc[f][0], acc[f][1]);
        *(float2*)&pacc[(size_t)(g + 8) * FO + col] = make_float2(acc[f][2], acc[f][3]);
    }
}

// ============================================================
// Kernel D: combine halves, normalize, ELU, store
// ============================================================
__global__ __launch_bounds__(256) void kernelD(float* __restrict__ out) {
    int idx = blockIdx.x * 256 + threadIdx.x;
    int row = idx >> 4;
    float l  = g_pl[row] + g_pl[BB * NN + row];
    float rl = 1.0f / l;
    float4 a0 = *(const float4*)(g_pacc + (size_t)idx * 4);
    float4 a1 = *(const float4*)(g_pacc + (size_t)BB * NN * FO + (size_t)idx * 4);
    float4 r;
    r.x = (a0.x + a1.x) * rl; r.x = (r.x > 0.0f) ? r.x : expm1f(r.x);
    r.y = (a0.y + a1.y) * rl; r.y = (r.y > 0.0f) ? r.y : expm1f(r.y);
    r.z = (a0.z + a1.z) * rl; r.z = (r.z > 0.0f) ? r.z : expm1f(r.z);
    r.w = (a0.w + a1.w) * rl; r.w = (r.w > 0.0f) ? r.w : expm1f(r.w);
    *(float4*)(out + (size_t)idx * 4) = r;
}

// ============================================================
extern "C" void kernel_launch(void* const* d_in, const int* in_sizes, int n_in,
                              void* d_out, int out_size) {
    const float* h   = nullptr;
    const float* Wm  = nullptr;
    const float* av  = nullptr;
    const int*   adj = nullptr;
    for (int i = 0; i < n_in; i++) {
        switch (in_sizes[i]) {
            case BB * NN * FIN: h  = (const float*)d_in[i]; break;
            case FO * FIN:      Wm = (const float*)d_in[i]; break;
            case 2 * FO:        av = (const float*)d_in[i]; break;
            default:
                if (in_sizes[i] == (int)((size_t)BB * NN * NN))
                    adj = (const int*)d_in[i];
                break;
        }
    }
    float* out = (float*)d_out;

    cudaFuncSetAttribute(kernelC, cudaFuncAttributeMaxDynamicSharedMemorySize,
                         DSMEM_BYTES);

    kernelA<<<BB * NN / 32, 128>>>(h, Wm);
    kernelA2<<<dim3(NN / 64, BB), 256>>>(av);
    kernelB<<<BB, 256>>>();
    kernelC<<<dim3(2, NN / 128, BB), 512, DSMEM_BYTES>>>(adj);
    kernelD<<<BB * NN * FO / 4 / 256, 256>>>(out);
}

// round 17
// speedup vs baseline: 1.7124x; 1.0423x over previous
#include <cuda_runtime.h>
#include <cuda_bf16.h>
#include <math.h>

#define BB 8
#define NN 2048
#define FIN 256
#define FO 64
#define ALPHA 0.2f

typedef unsigned long long u64;
typedef unsigned int u32;

// ---- HMMA m16n8k16 bf16 (base PTX, compiles for compute_103) ----
__device__ __forceinline__ void mma_bf16(float* c, const u32* a, u32 b0, u32 b1) {
    asm("mma.sync.aligned.m16n8k16.row.col.f32.bf16.bf16.f32 "
        "{%0,%1,%2,%3}, {%4,%5,%6,%7}, {%8,%9}, {%0,%1,%2,%3};"
        : "+f"(c[0]), "+f"(c[1]), "+f"(c[2]), "+f"(c[3])
        : "r"(a[0]), "r"(a[1]), "r"(a[2]), "r"(a[3]), "r"(b0), "r"(b1));
}

// split float pair -> bf16 hi / lo pairs
__device__ __forceinline__ void split2(float x, float y, u32& hi, u32& lo) {
    __nv_bfloat162 h2 = __float22bfloat162_rn(make_float2(x, y));
    float2 hf = __bfloat1622float2(h2);
    __nv_bfloat162 l2 = __float22bfloat162_rn(make_float2(x - hf.x, y - hf.y));
    hi = *(u32*)&h2;
    lo = *(u32*)&l2;
}

// ---- scratch ----
__device__ float g_Wh[BB * NN * FO];
__device__ float g_s1[BB * NN];
__device__ float g_s2[BB * NN];
__device__ float g_s2max[BB];
__device__ __nv_bfloat16 g_WhT_hi[BB * FO * NN];   // [b][o][j]
__device__ __nv_bfloat16 g_WhT_lo[BB * FO * NN];
__device__ float g_pacc[2 * BB * NN * FO];          // j-half partials
__device__ float g_pl[2 * BB * NN];

#define SP 72   // smem tile stride (bf16): frag LDS bank = 4g+t, conflict-free

// ============================================================
// Kernel A: Wh = h @ W^T via HMMA bf16 3-term split (proven)
// ============================================================
__global__ __launch_bounds__(128) void kernelA(const float* __restrict__ h,
                                               const float* __restrict__ Wm) {
    __shared__ __align__(16) __nv_bfloat16 Ahi[32 * SP], Alo[32 * SP];
    __shared__ __align__(16) __nv_bfloat16 Bhi[64 * SP], Blo[64 * SP];

    const int tid  = threadIdx.x;
    const int wid  = tid >> 5, lane = tid & 31;
    const int g    = lane >> 2, t = lane & 3;
    const int r0   = blockIdx.x * 32;
    const int rg   = wid & 1;
    const int nh   = wid >> 1;

    float acc[4][4];
#pragma unroll
    for (int f = 0; f < 4; f++)
#pragma unroll
        for (int c = 0; c < 4; c++) acc[f][c] = 0.0f;

    const int arow = tid >> 2, afq = tid & 3;
    const int wo   = tid >> 1, wfh = tid & 1;

    for (int fc = 0; fc < FIN; fc += 64) {
        __syncthreads();
        {
            const float* hp = h + (size_t)(r0 + arow) * FIN + fc + afq * 16;
            __nv_bfloat16* dh = Ahi + arow * SP + afq * 16;
            __nv_bfloat16* dl = Alo + arow * SP + afq * 16;
#pragma unroll
            for (int q = 0; q < 4; q++) {
                float4 v = *(const float4*)(hp + q * 4);
                u32 h0, l0, h1, l1;
                split2(v.x, v.y, h0, l0);
                split2(v.z, v.w, h1, l1);
                *(u32*)(dh + q * 4)     = h0;
                *(u32*)(dh + q * 4 + 2) = h1;
                *(u32*)(dl + q * 4)     = l0;
                *(u32*)(dl + q * 4 + 2) = l1;
            }
        }
        {
            const float* wp = Wm + (size_t)wo * FIN + fc + wfh * 32;
            __nv_bfloat16* dh = Bhi + wo * SP + wfh * 32;
            __nv_bfloat16* dl = Blo + wo * SP + wfh * 32;
#pragma unroll
            for (int q = 0; q < 8; q++) {
                float4 v = *(const float4*)(wp + q * 4);
                u32 h0, l0, h1, l1;
                split2(v.x, v.y, h0, l0);
                split2(v.z, v.w, h1, l1);
                *(u32*)(dh + q * 4)     = h0;
                *(u32*)(dh + q * 4 + 2) = h1;
                *(u32*)(dl + q * 4)     = l0;
                *(u32*)(dl + q * 4 + 2) = l1;
            }
        }
        __syncthreads();

#pragma unroll
        for (int kf = 0; kf < 4; kf++) {
            int k0 = kf * 16;
            int ra = (rg * 16 + g) * SP + k0 + 2 * t;
            int rb = ra + 8 * SP;
            u32 ah[4], al[4];
            ah[0] = *(const u32*)&Ahi[ra];      ah[1] = *(const u32*)&Ahi[rb];
            ah[2] = *(const u32*)&Ahi[ra + 8];  ah[3] = *(const u32*)&Ahi[rb + 8];
            al[0] = *(const u32*)&Alo[ra];      al[1] = *(const u32*)&Alo[rb];
            al[2] = *(const u32*)&Alo[ra + 8];  al[3] = *(const u32*)&Alo[rb + 8];
#pragma unroll
            for (int f = 0; f < 4; f++) {
                int nf = nh * 4 + f;
                int bo = (nf * 8 + g) * SP + k0 + 2 * t;
                u32 bh0 = *(const u32*)&Bhi[bo], bh1 = *(const u32*)&Bhi[bo + 8];
                u32 bl0 = *(const u32*)&Blo[bo], bl1 = *(const u32*)&Blo[bo + 8];
                mma_bf16(acc[f], ah, bh0, bh1);
                mma_bf16(acc[f], al, bh0, bh1);
                mma_bf16(acc[f], ah, bl0, bl1);
            }
        }
    }

    float* whp = g_Wh + (size_t)(r0 + rg * 16) * FO;
#pragma unroll
    for (int f = 0; f < 4; f++) {
        int col = (nh * 4 + f) * 8 + 2 * t;
        *(float2*)&whp[(size_t)g * FO + col]       = make_float2(acc[f][0], acc[f][1]);
        *(float2*)&whp[(size_t)(g + 8) * FO + col] = make_float2(acc[f][2], acc[f][3]);
    }
}

// ============================================================
// Kernel A2: Wh -> WhT[b][o][j] bf16 hi+lo, FUSED s1/s2 (proven)
// ============================================================
__global__ __launch_bounds__(256) void kernelA2(const float* __restrict__ av) {
    __shared__ float sm[64 * 65];
    const int tid = threadIdx.x;
    const int j0  = blockIdx.x * 64;
    const int b   = blockIdx.y;

    {
        int j = tid >> 2, u = tid & 3;
        const float* src = g_Wh + ((size_t)b * NN + j0 + j) * FO + u * 16;
        float* dst = sm + j * 65 + u * 16;
        float s1p = 0.0f, s2p = 0.0f;
#pragma unroll
        for (int q = 0; q < 4; q++) {
            float4 v = *(const float4*)(src + q * 4);
            dst[q * 4 + 0] = v.x;
            dst[q * 4 + 1] = v.y;
            dst[q * 4 + 2] = v.z;
            dst[q * 4 + 3] = v.w;
            int o = u * 16 + q * 4;
            s1p += v.x * __ldg(av + o)     + v.y * __ldg(av + o + 1)
                 + v.z * __ldg(av + o + 2) + v.w * __ldg(av + o + 3);
            s2p += v.x * __ldg(av + FO + o)     + v.y * __ldg(av + FO + o + 1)
                 + v.z * __ldg(av + FO + o + 2) + v.w * __ldg(av + FO + o + 3);
        }
        s1p += __shfl_down_sync(0xffffffffu, s1p, 2, 4);
        s1p += __shfl_down_sync(0xffffffffu, s1p, 1, 4);
        s2p += __shfl_down_sync(0xffffffffu, s2p, 2, 4);
        s2p += __shfl_down_sync(0xffffffffu, s2p, 1, 4);
        if (u == 0) { g_s1[b * NN + j0 + j] = s1p; g_s2[b * NN + j0 + j] = s2p; }
    }
    __syncthreads();
    {
        int o = tid >> 2, q = tid & 3;
        u32 hiw[8], low[8];
#pragma unroll
        for (int p = 0; p < 8; p++) {
            float f0 = sm[(q * 16 + 2 * p)     * 65 + o];
            float f1 = sm[(q * 16 + 2 * p + 1) * 65 + o];
            split2(f0, f1, hiw[p], low[p]);
        }
        size_t idx = ((size_t)b * FO + o) * NN + j0 + q * 16;
        *(uint4*)(g_WhT_hi + idx)     = make_uint4(hiw[0], hiw[1], hiw[2], hiw[3]);
        *(uint4*)(g_WhT_hi + idx + 8) = make_uint4(hiw[4], hiw[5], hiw[6], hiw[7]);
        *(uint4*)(g_WhT_lo + idx)     = make_uint4(low[0], low[1], low[2], low[3]);
        *(uint4*)(g_WhT_lo + idx + 8) = make_uint4(low[4], low[5], low[6], low[7]);
    }
}

// ============================================================
// Kernel B: per-batch max of s2
// ============================================================
__global__ void kernelB() {
    __shared__ float red[256];
    int b = blockIdx.x, tid = threadIdx.x;
    float m = -1e30f;
    for (int j = tid; j < NN; j += 256) m = fmaxf(m, g_s2[b * NN + j]);
    red[tid] = m;
    __syncthreads();
    for (int s = 128; s > 0; s >>= 1) {
        if (tid < s) red[tid] = fmaxf(red[tid], red[tid + s]);
        __syncthreads();
    }
    if (tid == 0) g_s2max[b] = red[0];
}

// ============================================================
// Kernel C: masked softmax + P@Wh via HMMA. R15 shape (i-tile
// 128, 512 thr, launch_bounds(512,2) -> regs<=64) now DOUBLE-
// BUFFERED with ONE sync per chunk: stage(c)->sync->mma(c),
// buffers alternate. Hazard-free: stage(c+2) is behind
// sync(c+1), which is behind every warp's mma(c). Warps
// finishing mma(c) immediately issue chunk-(c+1) adj LDGs ->
// DRAM latency overlaps other warps' MMAs. Smem 2x55296 =
// 110592 B -> still 2 blocks/SM. adj LDGs batched first (MLP 4).
// ============================================================
#define STAGE_ELEMS (384 * SP)             // bf16 elems per stage
#define DSMEM_BYTES (2 * STAGE_ELEMS * 2)  // 110592 B

__global__ __launch_bounds__(512, 2) void kernelC(const int* __restrict__ adj) {
    extern __shared__ __align__(16) __nv_bfloat16 dsm[];
    __shared__ float ls[128];

    const int tid  = threadIdx.x;
    const int wid  = tid >> 5, lane = tid & 31;
    const int g    = lane >> 2, t = lane & 3;
    const int jh   = blockIdx.x;
    const int i0   = blockIdx.y * 128;
    const int b    = blockIdx.z;
    const int j0   = jh * (NN / 2);

    // phase-1 mapping: 4 rows x 4 j per thread
    const int rq = tid >> 4;        // 0..31 -> rows rq*4..+3
    const int jq = tid & 15;        // j = jq*4..+3
    // mma mapping: 16 warps = 8 rowgroups x 2 n-halves
    const int rg = wid & 7, nh = wid >> 3;
    // W staging: uint4 = 8 bf16 per thread (64 rows x 8 chunks)
    const int so = tid >> 3, sq = tid & 7;

    const float M = g_s2max[b];
    float s1r[4], lsum[4];
#pragma unroll
    for (int k = 0; k < 4; k++) {
        s1r[k]  = __ldg(&g_s1[b * NN + i0 + rq * 4 + k]);
        lsum[k] = 0.0f;
    }

    const int*   adjb = adj + ((size_t)b * NN + i0) * NN;
    const float* s2b  = g_s2 + b * NN;
    const __nv_bfloat16* bhiB = g_WhT_hi + (size_t)b * FO * NN;
    const __nv_bfloat16* bloB = g_WhT_lo + (size_t)b * FO * NN;

    float acc[4][4];
#pragma unroll
    for (int f = 0; f < 4; f++)
#pragma unroll
        for (int c = 0; c < 4; c++) acc[f][c] = 0.0f;

    for (int tch = 0; tch < NN / 2 / 64; tch++) {
        const int jt = j0 + tch * 64;
        __nv_bfloat16* buf = dsm + (tch & 1) * STAGE_ELEMS;
        __nv_bfloat16* Phi = buf;
        __nv_bfloat16* Plo = buf + 128 * SP;
        __nv_bfloat16* Whi = buf + 256 * SP;
        __nv_bfloat16* Wlo = buf + 320 * SP;

        // ---- issue all gmem loads first (MLP: 4 adj + s2 + 2 W) ----
        int4 a4[4];
#pragma unroll
        for (int k = 0; k < 4; k++)
            a4[k] = *(const int4*)(adjb + (size_t)(rq * 4 + k) * NN + jt + jq * 4);
        float4 s2j = *(const float4*)(s2b + jt + jq * 4);
        uint4 wh = *(const uint4*)(bhiB + (size_t)so * NN + jt + sq * 8);
        uint4 wl = *(const uint4*)(bloB + (size_t)so * NN + jt + sq * 8);

        // ---- stage W tiles ----
        *(uint4*)&Whi[so * SP + sq * 8] = wh;
        *(uint4*)&Wlo[so * SP + sq * 8] = wl;

        // ---- phase 1: p = exp(LR(s1+s2)-m) masked, hi/lo split ----
#pragma unroll
        for (int k = 0; k < 4; k++) {
            int i = rq * 4 + k;
            int4 a = a4[k];
            float s1 = s1r[k];
            float tt = s1 + M;
            float mi = fmaxf(tt, ALPHA * tt);
            float e0 = s1 + s2j.x, e1 = s1 + s2j.y;
            float e2 = s1 + s2j.z, e3 = s1 + s2j.w;
            e0 = fmaxf(e0, ALPHA * e0);
            e1 = fmaxf(e1, ALPHA * e1);
            e2 = fmaxf(e2, ALPHA * e2);
            e3 = fmaxf(e3, ALPHA * e3);
            float p0 = (a.x > 0) ? __expf(e0 - mi) : 0.0f;
            float p1 = (a.y > 0) ? __expf(e1 - mi) : 0.0f;
            float p2 = (a.z > 0) ? __expf(e2 - mi) : 0.0f;
            float p3 = (a.w > 0) ? __expf(e3 - mi) : 0.0f;
            lsum[k] += (p0 + p1) + (p2 + p3);
            u32 h0, l0, h1, l1;
            split2(p0, p1, h0, l0);
            split2(p2, p3, h1, l1);
            *(u32*)&Phi[i * SP + jq * 4]     = h0;
            *(u32*)&Phi[i * SP + jq * 4 + 2] = h1;
            *(u32*)&Plo[i * SP + jq * 4]     = l0;
            *(u32*)&Plo[i * SP + jq * 4 + 2] = l1;
        }
        __syncthreads();

        // ---- phase 2: HMMA 3-term, 16 warps ----
#pragma unroll
        for (int kf = 0; kf < 4; kf++) {
            int k0 = kf * 16;
            int ra = (rg * 16 + g) * SP + k0 + 2 * t;
            int rb = ra + 8 * SP;
            u32 ah[4], al[4];
            ah[0] = *(const u32*)&Phi[ra];      ah[1] = *(const u32*)&Phi[rb];
            ah[2] = *(const u32*)&Phi[ra + 8];  ah[3] = *(const u32*)&Phi[rb + 8];
            al[0] = *(const u32*)&Plo[ra];      al[1] = *(const u32*)&Plo[rb];
            al[2] = *(const u32*)&Plo[ra + 8];  al[3] = *(const u32*)&Plo[rb + 8];
#pragma unroll
            for (int f = 0; f < 4; f++) {
                int nf = nh * 4 + f;
                int bo = (nf * 8 + g) * SP + k0 + 2 * t;
                u32 bh0 = *(const u32*)&Whi[bo], bh1 = *(const u32*)&Whi[bo + 8];
                u32 bl0 = *(const u32*)&Wlo[bo], bl1 = *(const u32*)&Wlo[bo + 8];
                mma_bf16(acc[f], ah, bh0, bh1);
                mma_bf16(acc[f], al, bh0, bh1);
                mma_bf16(acc[f], ah, bl0, bl1);
            }
        }
        // no second sync: next stage writes the OTHER buffer
    }

    // ---- row sums: reduce over 16 j-lanes ----
#pragma unroll
    for (int k = 0; k < 4; k++) {
        float v = lsum[k];
#pragma unroll
        for (int off = 8; off >= 1; off >>= 1)
            v += __shfl_down_sync(0xffffffffu, v, off, 16);
        if (jq == 0) ls[rq * 4 + k] = v;
    }
    __syncthreads();
    if (tid < 128)
        g_pl[jh * BB * NN + b * NN + i0 + tid] = ls[tid];

    // ---- store partials ----
    float* pacc = g_pacc + (size_t)jh * BB * NN * FO
                + ((size_t)b * NN + i0 + rg * 16) * FO;
#pragma unroll
    for (int f = 0; f < 4; f++) {
        int col = (nh * 4 + f) * 8 + 2 * t;
        *(float2*)&pacc[(size_t)g * FO + col]       = make_float2(acc[f][0], acc[f][1]);
        *(float2*)&pacc[(size_t)(g + 8) * FO + col] = make_float2(acc[f][2], acc[f][3]);
    }
}

// ============================================================
// Kernel D: combine halves, normalize, ELU, store
// ============================================================
__global__ __launch_bounds__(256) void kernelD(float* __restrict__ out) {
    int idx = blockIdx.x * 256 + threadIdx.x;
    int row = idx >> 4;
    float l  = g_pl[row] + g_pl[BB * NN + row];
    float rl = 1.0f / l;
    float4 a0 = *(const float4*)(g_pacc + (size_t)idx * 4);
    float4 a1 = *(const float4*)(g_pacc + (size_t)BB * NN * FO + (size_t)idx * 4);
    float4 r;
    r.x = (a0.x + a1.x) * rl; r.x = (r.x > 0.0f) ? r.x : expm1f(r.x);
    r.y = (a0.y + a1.y) * rl; r.y = (r.y > 0.0f) ? r.y : expm1f(r.y);
    r.z = (a0.z + a1.z) * rl; r.z = (r.z > 0.0f) ? r.z : expm1f(r.z);
    r.w = (a0.w + a1.w) * rl; r.w = (r.w > 0.0f) ? r.w : expm1f(r.w);
    *(float4*)(out + (size_t)idx * 4) = r;
}

// ============================================================
extern "C" void kernel_launch(void* const* d_in, const int* in_sizes, int n_in,
                              void* d_out, int out_size) {
    const float* h   = nullptr;
    const float* Wm  = nullptr;
    const float* av  = nullptr;
    const int*   adj = nullptr;
    for (int i = 0; i < n_in; i++) {
        switch (in_sizes[i]) {
            case BB * NN * FIN: h  = (const float*)d_in[i]; break;
            case FO * FIN:      Wm = (const float*)d_in[i]; break;
            case 2 * FO:        av = (const float*)d_in[i]; break;
            default:
                if (in_sizes[i] == (int)((size_t)BB * NN * NN))
                    adj = (const int*)d_in[i];
                break;
        }
    }
    float* out = (float*)d_out;

    cudaFuncSetAttribute(kernelC, cudaFuncAttributeMaxDynamicSharedMemorySize,
                         DSMEM_BYTES);

    kernelA<<<BB * NN / 32, 128>>>(h, Wm);
    kernelA2<<<dim3(NN / 64, BB), 256>>>(av);
    kernelB<<<BB, 256>>>();
    kernelC<<<dim3(2, NN / 128, BB), 512, DSMEM_BYTES>>>(adj);
    kernelD<<<BB * NN * FO / 4 / 256, 256>>>(out);
}